// round 8
// baseline (speedup 1.0000x reference)
#include <cuda_runtime.h>
#include <cuda_fp16.h>
#include <cstdint>

#define FDIM 64
#define TPB  128
#define RPC  64          // rows per CTA (4 warps x 16 rows)
#define AMAX 48
#define TLEN 2048
#define WSTR 36          // uint2 stride per n-row of W tiles (4r+q bank-distinct)

#define SMEM_W_BYTES (2*64*WSTR*8)     // 36864
#define SMEM_S_BYTES (AMAX*RPC*4)      // 12288
#define SMEM_TOTAL   (SMEM_W_BYTES + SMEM_S_BYTES)

__device__ __forceinline__ float sigmoidf(float x) {
    return __fdividef(1.0f, 1.0f + __expf(-x));
}

// split fp32 pair into packed fp16 hi + fp16 residual lo (e0 -> low half)
__device__ __forceinline__ void split_pack(float e0, float e1,
                                           uint32_t& hi, uint32_t& lo) {
    __half2 hp = __floats2half2_rn(e0, e1);
    float f0 = __low2float(hp), f1 = __high2float(hp);
    __half2 lp = __floats2half2_rn(e0 - f0, e1 - f1);
    hi = *reinterpret_cast<uint32_t*>(&hp);
    lo = *reinterpret_cast<uint32_t*>(&lp);
}

#define MMA16(d,a,b0,b1) \
    asm("mma.sync.aligned.m16n8k16.row.col.f32.f16.f16.f32 " \
        "{%0,%1,%2,%3},{%4,%5,%6,%7},{%8,%9},{%0,%1,%2,%3};" \
        : "+f"((d)[0]),"+f"((d)[1]),"+f"((d)[2]),"+f"((d)[3]) \
        : "r"((a)[0]),"r"((a)[1]),"r"((a)[2]),"r"((a)[3]),"r"(b0),"r"(b1))

// d[nt][c] = Hw(16x64) @ W(64x64); A register-resident hi/lo, W pre-split in smem.
// nt pairs interleaved so the 3-term chains alternate between two accumulators.
__device__ __forceinline__ void gemm_f16(float (&d)[8][4],
                                         const uint32_t (&Ahi)[4][4],
                                         const uint32_t (&Alo)[4][4],
                                         const uint2* __restrict__ sWm,
                                         int r, int q)
{
    #pragma unroll
    for (int nt = 0; nt < 8; nt++)
        #pragma unroll
        for (int c = 0; c < 4; c++) d[nt][c] = 0.0f;

    #pragma unroll
    for (int ntp = 0; ntp < 4; ntp++) {
        const int nt0 = 2 * ntp, nt1 = nt0 + 1;
        const uint2* bp0 = sWm + (8 * nt0 + r) * WSTR + q;
        const uint2* bp1 = sWm + (8 * nt1 + r) * WSTR + q;
        #pragma unroll
        for (int kt = 0; kt < 4; kt++) {
            uint2 u00 = bp0[8 * kt], u01 = bp0[8 * kt + 4];
            uint2 u10 = bp1[8 * kt], u11 = bp1[8 * kt + 4];
            MMA16(d[nt0], Ahi[kt], u00.x, u01.x);
            MMA16(d[nt1], Ahi[kt], u10.x, u11.x);
            MMA16(d[nt0], Alo[kt], u00.x, u01.x);
            MMA16(d[nt1], Alo[kt], u10.x, u11.x);
            MMA16(d[nt0], Ahi[kt], u00.y, u01.y);
            MMA16(d[nt1], Ahi[kt], u10.y, u11.y);
        }
    }
}

extern __shared__ char smem_raw[];

__global__ void __launch_bounds__(TPB, 4) ContextBlock_kernel(
    const float* __restrict__ he,
    const float* __restrict__ W1,
    const float* __restrict__ W2,
    const int*   __restrict__ alen,
    float*       __restrict__ out,
    int n_rows)
{
    const int tid  = threadIdx.x;
    const int lane = tid & 31;
    const int wid  = tid >> 5;
    const int q    = lane & 3;
    const int r    = lane >> 2;

    uint2* sW = (uint2*)smem_raw;
    float* sS = (float*)(smem_raw + SMEM_W_BYTES);

    // ---- W prep: pre-split hi/lo fp16 pairs, B-fragment layout [m][n][kpair] ----
    for (int i = tid; i < 2 * 64 * 32; i += TPB) {
        int m   = i >> 11;
        int rem = i & 2047;
        int n = rem >> 5, kp = rem & 31;
        const float* W = m ? W2 : W1;
        float w0 = W[(2 * kp) * FDIM + n];
        float w1 = W[(2 * kp + 1) * FDIM + n];
        uint2 u;
        split_pack(w0, w1, u.x, u.y);
        sW[m * 64 * WSTR + n * WSTR + kp] = u;
    }

    // ---- identity ----
    const int ctaRow0 = blockIdx.x * RPC;
    const int t0cta   = ctaRow0 % TLEN;
    const float* bhe  = he + (size_t)(ctaRow0 - t0cta) * FDIM;

    int A = alen ? alen[0] : AMAX;
    if (A > AMAX) A = AMAX;

    // ---- init register-resident H state (16 rows/warp) from he ----
    const int warpRow = ctaRow0 + wid * 16;
    uint32_t Ahi[4][4], Alo[4][4];
    {
        const int R0 = min(warpRow + r, n_rows - 1);
        const int R1 = min(warpRow + r + 8, n_rows - 1);
        const float* p0 = he + (size_t)R0 * FDIM;
        const float* p1 = he + (size_t)R1 * FDIM;
        #pragma unroll
        for (int kt = 0; kt < 4; kt++) {
            int c0 = 16 * kt + 2 * q, c1 = c0 + 8;
            float2 e;
            e = *(const float2*)(p0 + c0); split_pack(e.x, e.y, Ahi[kt][0], Alo[kt][0]);
            e = *(const float2*)(p1 + c0); split_pack(e.x, e.y, Ahi[kt][1], Alo[kt][1]);
            e = *(const float2*)(p0 + c1); split_pack(e.x, e.y, Ahi[kt][2], Alo[kt][2]);
            e = *(const float2*)(p1 + c1); split_pack(e.x, e.y, Ahi[kt][3], Alo[kt][3]);
        }
    }
    __syncthreads();   // W tiles ready

    // ---- per-epi-row attention params (rows r, r+8 of warp block) ----
    int Lm[2], basem[2];
    #pragma unroll
    for (int m = 0; m < 2; m++) {
        int grow = warpRow + r + 8 * m;
        int tm = grow % TLEN;
        int Lv = min(A, max(tm, 1));
        Lm[m] = Lv;
        basem[m] = tm - Lv;
    }

    // ================= Pass 1: recurrence + scores (no smem H, no CTA syncs) ====
    float d[8][4];
    for (int a = 0; a < AMAX; a++) {
        // H' = sigmoid(H @ W1): output fragment == next A fragment, in-thread
        gemm_f16(d, Ahi, Alo, sW, r, q);
        #pragma unroll
        for (int kt = 0; kt < 4; kt++) {
            const float* d0 = d[2 * kt];
            const float* d1 = d[2 * kt + 1];
            split_pack(sigmoidf(d0[0]), sigmoidf(d0[1]), Ahi[kt][0], Alo[kt][0]);
            split_pack(sigmoidf(d0[2]), sigmoidf(d0[3]), Ahi[kt][1], Alo[kt][1]);
            split_pack(sigmoidf(d1[0]), sigmoidf(d1[1]), Ahi[kt][2], Alo[kt][2]);
            split_pack(sigmoidf(d1[2]), sigmoidf(d1[3]), Ahi[kt][3], Alo[kt][3]);
        }

        // Y = sigmoid(H' @ W2); score = Y . he[b, j(row,a)]
        gemm_f16(d, Ahi, Alo, sW + 64 * WSTR, r, q);

        const float* gp0 = bhe + (size_t)max(basem[0] + a, 0) * FDIM;
        const float* gp1 = bhe + (size_t)max(basem[1] + a, 0) * FDIM;
        float p0 = 0.f, p1 = 0.f;
        #pragma unroll
        for (int nt = 0; nt < 8; nt++) {
            float2 g0 = *(const float2*)(gp0 + nt * 8 + 2 * q);
            float2 g1 = *(const float2*)(gp1 + nt * 8 + 2 * q);
            p0 = fmaf(sigmoidf(d[nt][0]), g0.x, fmaf(sigmoidf(d[nt][1]), g0.y, p0));
            p1 = fmaf(sigmoidf(d[nt][2]), g1.x, fmaf(sigmoidf(d[nt][3]), g1.y, p1));
        }
        p0 += __shfl_xor_sync(0xFFFFFFFFu, p0, 1);
        p0 += __shfl_xor_sync(0xFFFFFFFFu, p0, 2);
        p1 += __shfl_xor_sync(0xFFFFFFFFu, p1, 1);
        p1 += __shfl_xor_sync(0xFFFFFFFFu, p1, 2);
        if (q == 0) {
            sS[a * RPC + wid * 16 + r]     = (a < Lm[0]) ? p0 : -1e30f;
            sS[a * RPC + wid * 16 + r + 8] = (a < Lm[1]) ? p1 : -1e30f;
        }
    }
    __syncthreads();

    // ========== Pass 2: softmax + gather; 2 threads per row (32 feats each) =====
    {
        const int rowIdx = tid & 63;
        const int half   = tid >> 6;
        const int row    = ctaRow0 + rowIdx;
        if (row < n_rows) {
            const int t   = row % TLEN;
            const int L   = min(A, max(t, 1));
            const int bse = t - L;

            float mx = -1e30f;
            for (int a = 0; a < AMAX; a++) mx = fmaxf(mx, sS[a * RPC + rowIdx]);

            float acc[32];
            #pragma unroll
            for (int j = 0; j < 32; j++) acc[j] = 0.0f;
            float ssum = 0.0f;
            const float* gb = bhe + half * 32;
            for (int a = 0; a < L; a++) {
                float w = __expf(sS[a * RPC + rowIdx] - mx);
                ssum += w;
                int jrow = max(bse + a, 0);
                const float4* g = (const float4*)(gb + (size_t)jrow * FDIM);
                #pragma unroll
                for (int c = 0; c < 8; c++) {
                    float4 gv = g[c];
                    acc[4*c+0] = fmaf(w, gv.x, acc[4*c+0]);
                    acc[4*c+1] = fmaf(w, gv.y, acc[4*c+1]);
                    acc[4*c+2] = fmaf(w, gv.z, acc[4*c+2]);
                    acc[4*c+3] = fmaf(w, gv.w, acc[4*c+3]);
                }
            }
            const float inv = __fdividef(1.0f, ssum);
            float4* o = (float4*)(out + (size_t)row * FDIM + half * 32);
            #pragma unroll
            for (int c = 0; c < 8; c++) {
                float4 v;
                v.x = acc[4*c+0] * inv; v.y = acc[4*c+1] * inv;
                v.z = acc[4*c+2] * inv; v.w = acc[4*c+3] * inv;
                o[c] = v;
            }
        }
    }
}

extern "C" void kernel_launch(void* const* d_in, const int* in_sizes, int n_in,
                              void* d_out, int out_size)
{
    const float* he   = (const float*)d_in[0];
    const float* W1   = (const float*)d_in[1];
    const float* W2   = (const float*)d_in[2];
    const int*   alen = (n_in >= 4) ? (const int*)d_in[3] : nullptr;
    float*       out  = (float*)d_out;

    const int n_rows = in_sizes[0] / FDIM;   // B*T

    cudaFuncSetAttribute(ContextBlock_kernel,
                         cudaFuncAttributeMaxDynamicSharedMemorySize, SMEM_TOTAL);
    const int grid = (n_rows + RPC - 1) / RPC;
    ContextBlock_kernel<<<grid, TPB, SMEM_TOTAL>>>(he, W1, W2, alen, out, n_rows);
}

// round 10
// speedup vs baseline: 1.0360x; 1.0360x over previous
#include <cuda_runtime.h>
#include <cuda_fp16.h>
#include <cstdint>

#define FDIM 64
#define TPB  128
#define RPC  128         // rows per CTA (4 warps x 32 rows)
#define AMAX 48
#define TLEN 2048
#define WSTR 36          // uint2 stride per n-row of W tiles (4r+q bank-distinct)

#define SMEM_W_BYTES (2*64*WSTR*8)     // 36864
#define SMEM_S_BYTES (AMAX*RPC*4)      // 24576
#define SMEM_TOTAL   (SMEM_W_BYTES + SMEM_S_BYTES)

__device__ __forceinline__ float sigmoidf(float x) {
    return __fdividef(1.0f, 1.0f + __expf(-x));
}

// split fp32 pair into packed fp16 hi + fp16 residual lo (e0 -> low half)
__device__ __forceinline__ void split_pack(float e0, float e1,
                                           uint32_t& hi, uint32_t& lo) {
    __half2 hp = __floats2half2_rn(e0, e1);
    float f0 = __low2float(hp), f1 = __high2float(hp);
    __half2 lp = __floats2half2_rn(e0 - f0, e1 - f1);
    hi = *reinterpret_cast<uint32_t*>(&hp);
    lo = *reinterpret_cast<uint32_t*>(&lp);
}

#define MMA16(d,a,b0,b1) \
    asm("mma.sync.aligned.m16n8k16.row.col.f32.f16.f16.f32 " \
        "{%0,%1,%2,%3},{%4,%5,%6,%7},{%8,%9},{%0,%1,%2,%3};" \
        : "+f"((d)[0]),"+f"((d)[1]),"+f"((d)[2]),"+f"((d)[3]) \
        : "r"((a)[0]),"r"((a)[1]),"r"((a)[2]),"r"((a)[3]),"r"(b0),"r"(b1))

// One nt-pair of the GEMM: dd[mt][np][4] += Hw(32x16seg) @ Wcols(16), 3-term f16
__device__ __forceinline__ void gemm_pair(float (&dd)[2][2][4],
                                          const uint32_t (&Ahi)[2][4][4],
                                          const uint32_t (&Alo)[2][4][4],
                                          const uint2* __restrict__ sWm,
                                          int ntp, int r, int q)
{
    #pragma unroll
    for (int mt = 0; mt < 2; mt++)
        #pragma unroll
        for (int np = 0; np < 2; np++)
            #pragma unroll
            for (int c = 0; c < 4; c++) dd[mt][np][c] = 0.0f;

    const uint2* bp0 = sWm + (16 * ntp + r) * WSTR + q;      // nt = 2*ntp
    const uint2* bp1 = sWm + (16 * ntp + 8 + r) * WSTR + q;  // nt = 2*ntp+1
    #pragma unroll
    for (int kt = 0; kt < 4; kt++) {
        uint2 u00 = bp0[8 * kt], u01 = bp0[8 * kt + 4];
        uint2 u10 = bp1[8 * kt], u11 = bp1[8 * kt + 4];
        // 4 independent accumulators per term -> dep distance 4
        MMA16(dd[0][0], Ahi[0][kt], u00.x, u01.x);
        MMA16(dd[0][1], Ahi[0][kt], u10.x, u11.x);
        MMA16(dd[1][0], Ahi[1][kt], u00.x, u01.x);
        MMA16(dd[1][1], Ahi[1][kt], u10.x, u11.x);
        MMA16(dd[0][0], Alo[0][kt], u00.x, u01.x);
        MMA16(dd[0][1], Alo[0][kt], u10.x, u11.x);
        MMA16(dd[1][0], Alo[1][kt], u00.x, u01.x);
        MMA16(dd[1][1], Alo[1][kt], u10.x, u11.x);
        MMA16(dd[0][0], Ahi[0][kt], u00.y, u01.y);
        MMA16(dd[0][1], Ahi[0][kt], u10.y, u11.y);
        MMA16(dd[1][0], Ahi[1][kt], u00.y, u01.y);
        MMA16(dd[1][1], Ahi[1][kt], u10.y, u11.y);
    }
}

extern __shared__ char smem_raw[];

__global__ void __launch_bounds__(TPB, 3) ContextBlock_kernel(
    const float* __restrict__ he,
    const float* __restrict__ W1,
    const float* __restrict__ W2,
    const int*   __restrict__ alen,
    float*       __restrict__ out,
    int n_rows)
{
    const int tid  = threadIdx.x;
    const int lane = tid & 31;
    const int wid  = tid >> 5;
    const int q    = lane & 3;
    const int r    = lane >> 2;

    uint2* sW = (uint2*)smem_raw;
    float* sS = (float*)(smem_raw + SMEM_W_BYTES);

    // ---- W prep: pre-split hi/lo fp16 pairs, B-fragment layout [m][n][kpair] ----
    for (int i = tid; i < 2 * 64 * 32; i += TPB) {
        int m   = i >> 11;
        int rem = i & 2047;
        int n = rem >> 5, kp = rem & 31;
        const float* W = m ? W2 : W1;
        float w0 = W[(2 * kp) * FDIM + n];
        float w1 = W[(2 * kp + 1) * FDIM + n];
        uint2 u;
        split_pack(w0, w1, u.x, u.y);
        sW[m * 64 * WSTR + n * WSTR + kp] = u;
    }

    // ---- identity ----
    const int ctaRow0 = blockIdx.x * RPC;
    const int t0cta   = ctaRow0 % TLEN;
    const float* bhe  = he + (size_t)(ctaRow0 - t0cta) * FDIM;

    int A = alen ? alen[0] : AMAX;
    if (A > AMAX) A = AMAX;

    // ---- init register-resident H state (32 rows/warp) from he ----
    const int warpRow = ctaRow0 + wid * 32;
    uint32_t Ahi[2][4][4], Alo[2][4][4];
    #pragma unroll
    for (int mt = 0; mt < 2; mt++) {
        const int R0 = min(warpRow + r + 16 * mt, n_rows - 1);
        const int R1 = min(R0 + 8, n_rows - 1);
        const float* p0 = he + (size_t)R0 * FDIM;
        const float* p1 = he + (size_t)R1 * FDIM;
        #pragma unroll
        for (int kt = 0; kt < 4; kt++) {
            int c0 = 16 * kt + 2 * q, c1 = c0 + 8;
            float2 e;
            e = *(const float2*)(p0 + c0); split_pack(e.x, e.y, Ahi[mt][kt][0], Alo[mt][kt][0]);
            e = *(const float2*)(p1 + c0); split_pack(e.x, e.y, Ahi[mt][kt][1], Alo[mt][kt][1]);
            e = *(const float2*)(p0 + c1); split_pack(e.x, e.y, Ahi[mt][kt][2], Alo[mt][kt][2]);
            e = *(const float2*)(p1 + c1); split_pack(e.x, e.y, Ahi[mt][kt][3], Alo[mt][kt][3]);
        }
    }
    __syncthreads();   // W tiles ready

    // ---- per-epi-row attention params (rows r+8m of warp block) ----
    int Lm[4], basem[4];
    #pragma unroll
    for (int m = 0; m < 4; m++) {
        int grow = warpRow + r + 8 * m;
        int tm = grow % TLEN;
        int Lv = min(A, max(tm, 1));
        Lm[m] = Lv;
        basem[m] = tm - Lv;
    }

    // ================= Pass 1: recurrence + scores =================
    for (int a = 0; a < AMAX; a++) {
        // ---- H' = sigmoid(H @ W1), fused per nt-pair into next A fragments ----
        uint32_t Nhi[2][4][4], Nlo[2][4][4];
        #pragma unroll
        for (int ntp = 0; ntp < 4; ntp++) {
            float dd[2][2][4];
            gemm_pair(dd, Ahi, Alo, sW, ntp, r, q);
            #pragma unroll
            for (int mt = 0; mt < 2; mt++) {
                split_pack(sigmoidf(dd[mt][0][0]), sigmoidf(dd[mt][0][1]),
                           Nhi[mt][ntp][0], Nlo[mt][ntp][0]);
                split_pack(sigmoidf(dd[mt][0][2]), sigmoidf(dd[mt][0][3]),
                           Nhi[mt][ntp][1], Nlo[mt][ntp][1]);
                split_pack(sigmoidf(dd[mt][1][0]), sigmoidf(dd[mt][1][1]),
                           Nhi[mt][ntp][2], Nlo[mt][ntp][2]);
                split_pack(sigmoidf(dd[mt][1][2]), sigmoidf(dd[mt][1][3]),
                           Nhi[mt][ntp][3], Nlo[mt][ntp][3]);
            }
        }
        #pragma unroll
        for (int mt = 0; mt < 2; mt++)
            #pragma unroll
            for (int kt = 0; kt < 4; kt++)
                #pragma unroll
                for (int j = 0; j < 4; j++) {
                    Ahi[mt][kt][j] = Nhi[mt][kt][j];
                    Alo[mt][kt][j] = Nlo[mt][kt][j];
                }

        // ---- Y = sigmoid(H' @ W2), fused per nt-pair into score dot-product ----
        const float* gp[4];
        #pragma unroll
        for (int m = 0; m < 4; m++) {
            int j = basem[m] + a;
            j = max(j, 0);
            gp[m] = bhe + (size_t)j * FDIM;
        }
        float p[4] = {0.f, 0.f, 0.f, 0.f};
        #pragma unroll
        for (int ntp = 0; ntp < 4; ntp++) {
            float dd[2][2][4];
            gemm_pair(dd, Ahi, Alo, sW + 64 * WSTR, ntp, r, q);
            #pragma unroll
            for (int np = 0; np < 2; np++) {
                const int col = (2 * ntp + np) * 8 + 2 * q;
                #pragma unroll
                for (int m = 0; m < 4; m++) {
                    int mt = m >> 1, cp = (m & 1) * 2;
                    float y0 = sigmoidf(dd[mt][np][cp + 0]);
                    float y1 = sigmoidf(dd[mt][np][cp + 1]);
                    float2 g = *(const float2*)(gp[m] + col);
                    p[m] = fmaf(y0, g.x, fmaf(y1, g.y, p[m]));
                }
            }
        }
        #pragma unroll
        for (int m = 0; m < 4; m++) {
            p[m] += __shfl_xor_sync(0xFFFFFFFFu, p[m], 1);
            p[m] += __shfl_xor_sync(0xFFFFFFFFu, p[m], 2);
        }
        if (q == 0) {
            #pragma unroll
            for (int m = 0; m < 4; m++)
                sS[a * RPC + wid * 32 + r + 8 * m] = (a < Lm[m]) ? p[m] : -1e30f;
        }
    }
    __syncthreads();

    // ================= Pass 2: softmax + weighted gather (1 thread/row) =========
    {
        const int row  = ctaRow0 + tid;
        if (row < n_rows) {
            const int t   = row % TLEN;
            const int L   = min(A, max(t, 1));
            const int bse = t - L;

            float mx = -1e30f;
            for (int a = 0; a < AMAX; a++) mx = fmaxf(mx, sS[a * RPC + tid]);

            float acc[FDIM];
            #pragma unroll
            for (int j = 0; j < FDIM; j++) acc[j] = 0.0f;
            float ssum = 0.0f;
            for (int a = 0; a < L; a++) {
                float w = __expf(sS[a * RPC + tid] - mx);
                ssum += w;
                int jrow = max(bse + a, 0);
                const float4* g = (const float4*)(bhe + (size_t)jrow * FDIM);
                #pragma unroll
                for (int c = 0; c < 16; c++) {
                    float4 gv = g[c];
                    acc[4*c+0] = fmaf(w, gv.x, acc[4*c+0]);
                    acc[4*c+1] = fmaf(w, gv.y, acc[4*c+1]);
                    acc[4*c+2] = fmaf(w, gv.z, acc[4*c+2]);
                    acc[4*c+3] = fmaf(w, gv.w, acc[4*c+3]);
                }
            }
            const float inv = __fdividef(1.0f, ssum);
            float4* o = (float4*)(out + (size_t)row * FDIM);
            #pragma unroll
            for (int c = 0; c < 16; c++) {
                float4 v;
                v.x = acc[4*c+0] * inv; v.y = acc[4*c+1] * inv;
                v.z = acc[4*c+2] * inv; v.w = acc[4*c+3] * inv;
                o[c] = v;
            }
        }
    }
}

extern "C" void kernel_launch(void* const* d_in, const int* in_sizes, int n_in,
                              void* d_out, int out_size)
{
    const float* he   = (const float*)d_in[0];
    const float* W1   = (const float*)d_in[1];
    const float* W2   = (const float*)d_in[2];
    const int*   alen = (n_in >= 4) ? (const int*)d_in[3] : nullptr;
    float*       out  = (float*)d_out;

    const int n_rows = in_sizes[0] / FDIM;   // B*T

    cudaFuncSetAttribute(ContextBlock_kernel,
                         cudaFuncAttributeMaxDynamicSharedMemorySize, SMEM_TOTAL);
    const int grid = (n_rows + RPC - 1) / RPC;
    ContextBlock_kernel<<<grid, TPB, SMEM_TOTAL>>>(he, W1, W2, alen, out, n_rows);
}

// round 13
// speedup vs baseline: 1.1944x; 1.1529x over previous
#include <cuda_runtime.h>
#include <cuda_fp16.h>
#include <cstdint>

#define FDIM 64
#define TPB  128
#define RPC  128         // rows per CTA (4 warps x 32 rows)
#define AMAX 48
#define TLEN 2048
#define WSTR 36          // uint2 stride per n-row of W tiles (4r+q bank-distinct)

#define SMEM_W_BYTES (2*64*WSTR*8)     // 36864
#define SMEM_S_BYTES (AMAX*RPC*4)      // 24576
#define SMEM_TOTAL   (SMEM_W_BYTES + SMEM_S_BYTES)

// sigmoid(x) = 0.5 + 0.5*tanh(x/2): single MUFU op, deterministic
__device__ __forceinline__ float sigmoidf(float x) {
    float h = 0.5f * x, t;
    asm("tanh.approx.f32 %0, %1;" : "=f"(t) : "f"(h));
    return fmaf(0.5f, t, 0.5f);
}

// split fp32 pair into packed fp16 hi + fp16 residual lo (e0 -> low half)
__device__ __forceinline__ void split_pack(float e0, float e1,
                                           uint32_t& hi, uint32_t& lo) {
    __half2 hp = __floats2half2_rn(e0, e1);
    float f0 = __low2float(hp), f1 = __high2float(hp);
    __half2 lp = __floats2half2_rn(e0 - f0, e1 - f1);
    hi = *reinterpret_cast<uint32_t*>(&hp);
    lo = *reinterpret_cast<uint32_t*>(&lp);
}

#define MMA16(d,a,b0,b1) \
    asm("mma.sync.aligned.m16n8k16.row.col.f32.f16.f16.f32 " \
        "{%0,%1,%2,%3},{%4,%5,%6,%7},{%8,%9},{%0,%1,%2,%3};" \
        : "+f"((d)[0]),"+f"((d)[1]),"+f"((d)[2]),"+f"((d)[3]) \
        : "r"((a)[0]),"r"((a)[1]),"r"((a)[2]),"r"((a)[3]),"r"(b0),"r"(b1))

// Single-matrix nt-pair chunk (prologue only)
__device__ __forceinline__ void gemm_chunk(float (&dd)[2][2][4],
                                           const uint32_t (&Ahi)[2][4][4],
                                           const uint32_t (&Alo)[2][4][4],
                                           const uint2* __restrict__ sWm,
                                           int ntp, int r, int q)
{
    #pragma unroll
    for (int mt = 0; mt < 2; mt++)
        #pragma unroll
        for (int np = 0; np < 2; np++)
            #pragma unroll
            for (int c = 0; c < 4; c++) dd[mt][np][c] = 0.0f;

    const uint2* bp0 = sWm + (16 * ntp + r) * WSTR + q;
    const uint2* bp1 = sWm + (16 * ntp + 8 + r) * WSTR + q;
    #pragma unroll
    for (int kt = 0; kt < 4; kt++) {
        uint2 u00 = bp0[8 * kt], u01 = bp0[8 * kt + 4];
        uint2 u10 = bp1[8 * kt], u11 = bp1[8 * kt + 4];
        MMA16(dd[0][0], Ahi[0][kt], u00.x, u01.x);
        MMA16(dd[0][1], Ahi[0][kt], u10.x, u11.x);
        MMA16(dd[1][0], Ahi[1][kt], u00.x, u01.x);
        MMA16(dd[1][1], Ahi[1][kt], u10.x, u11.x);
        MMA16(dd[0][0], Alo[0][kt], u00.x, u01.x);
        MMA16(dd[0][1], Alo[0][kt], u10.x, u11.x);
        MMA16(dd[1][0], Alo[1][kt], u00.x, u01.x);
        MMA16(dd[1][1], Alo[1][kt], u10.x, u11.x);
        MMA16(dd[0][0], Ahi[0][kt], u00.y, u01.y);
        MMA16(dd[0][1], Ahi[0][kt], u10.y, u11.y);
        MMA16(dd[1][0], Ahi[1][kt], u00.y, u01.y);
        MMA16(dd[1][1], Ahi[1][kt], u10.y, u11.y);
    }
}

// Dual-matrix nt-pair chunk: d1 += A@W1cols, d2 += A@W2cols interleaved.
// 8 independent accumulator chains -> dep distance 8 between same-chain MMAs.
__device__ __forceinline__ void dual_chunk(float (&d1)[2][2][4],
                                           float (&d2)[2][2][4],
                                           const uint32_t (&Ahi)[2][4][4],
                                           const uint32_t (&Alo)[2][4][4],
                                           const uint2* __restrict__ sW1,
                                           const uint2* __restrict__ sW2,
                                           int ntp, int r, int q)
{
    #pragma unroll
    for (int mt = 0; mt < 2; mt++)
        #pragma unroll
        for (int np = 0; np < 2; np++)
            #pragma unroll
            for (int c = 0; c < 4; c++) { d1[mt][np][c] = 0.0f; d2[mt][np][c] = 0.0f; }

    const uint2* ap0 = sW1 + (16 * ntp + r) * WSTR + q;
    const uint2* ap1 = sW1 + (16 * ntp + 8 + r) * WSTR + q;
    const uint2* bp0 = sW2 + (16 * ntp + r) * WSTR + q;
    const uint2* bp1 = sW2 + (16 * ntp + 8 + r) * WSTR + q;
    #pragma unroll
    for (int kt = 0; kt < 4; kt++) {
        uint2 u00 = ap0[8 * kt], u01 = ap0[8 * kt + 4];
        uint2 u10 = ap1[8 * kt], u11 = ap1[8 * kt + 4];
        uint2 v00 = bp0[8 * kt], v01 = bp0[8 * kt + 4];
        uint2 v10 = bp1[8 * kt], v11 = bp1[8 * kt + 4];
        // term hi*hi — 8 independent chains
        MMA16(d1[0][0], Ahi[0][kt], u00.x, u01.x);
        MMA16(d1[0][1], Ahi[0][kt], u10.x, u11.x);
        MMA16(d1[1][0], Ahi[1][kt], u00.x, u01.x);
        MMA16(d1[1][1], Ahi[1][kt], u10.x, u11.x);
        MMA16(d2[0][0], Ahi[0][kt], v00.x, v01.x);
        MMA16(d2[0][1], Ahi[0][kt], v10.x, v11.x);
        MMA16(d2[1][0], Ahi[1][kt], v00.x, v01.x);
        MMA16(d2[1][1], Ahi[1][kt], v10.x, v11.x);
        // term lo*hi
        MMA16(d1[0][0], Alo[0][kt], u00.x, u01.x);
        MMA16(d1[0][1], Alo[0][kt], u10.x, u11.x);
        MMA16(d1[1][0], Alo[1][kt], u00.x, u01.x);
        MMA16(d1[1][1], Alo[1][kt], u10.x, u11.x);
        MMA16(d2[0][0], Alo[0][kt], v00.x, v01.x);
        MMA16(d2[0][1], Alo[0][kt], v10.x, v11.x);
        MMA16(d2[1][0], Alo[1][kt], v00.x, v01.x);
        MMA16(d2[1][1], Alo[1][kt], v10.x, v11.x);
        // term hi*lo
        MMA16(d1[0][0], Ahi[0][kt], u00.y, u01.y);
        MMA16(d1[0][1], Ahi[0][kt], u10.y, u11.y);
        MMA16(d1[1][0], Ahi[1][kt], u00.y, u01.y);
        MMA16(d1[1][1], Ahi[1][kt], u10.y, u11.y);
        MMA16(d2[0][0], Ahi[0][kt], v00.y, v01.y);
        MMA16(d2[0][1], Ahi[0][kt], v10.y, v11.y);
        MMA16(d2[1][0], Ahi[1][kt], v00.y, v01.y);
        MMA16(d2[1][1], Ahi[1][kt], v10.y, v11.y);
    }
}

extern __shared__ char smem_raw[];

__global__ void __launch_bounds__(TPB) ContextBlock_kernel(
    const float* __restrict__ he,
    const float* __restrict__ W1,
    const float* __restrict__ W2,
    const int*   __restrict__ alen,
    float*       __restrict__ out,
    int n_rows)
{
    const int tid  = threadIdx.x;
    const int lane = tid & 31;
    const int wid  = tid >> 5;
    const int q    = lane & 3;
    const int r    = lane >> 2;

    uint2* sW = (uint2*)smem_raw;
    float* sS = (float*)(smem_raw + SMEM_W_BYTES);

    // ---- W prep: pre-split hi/lo fp16 pairs, B-fragment layout [m][n][kpair] ----
    for (int i = tid; i < 2 * 64 * 32; i += TPB) {
        int m   = i >> 11;
        int rem = i & 2047;
        int n = rem >> 5, kp = rem & 31;
        const float* W = m ? W2 : W1;
        float w0 = W[(2 * kp) * FDIM + n];
        float w1 = W[(2 * kp + 1) * FDIM + n];
        uint2 u;
        split_pack(w0, w1, u.x, u.y);
        sW[m * 64 * WSTR + n * WSTR + kp] = u;
    }

    // ---- identity ----
    const int ctaRow0 = blockIdx.x * RPC;
    const int t0cta   = ctaRow0 % TLEN;
    const float* bhe  = he + (size_t)(ctaRow0 - t0cta) * FDIM;

    int A = alen ? alen[0] : AMAX;
    if (A > AMAX) A = AMAX;

    // ---- init register-resident H state (32 rows/warp) from he ----
    const int warpRow = ctaRow0 + wid * 32;
    uint32_t Ahi[2][4][4], Alo[2][4][4];
    #pragma unroll
    for (int mt = 0; mt < 2; mt++) {
        const int R0 = min(warpRow + r + 16 * mt, n_rows - 1);
        const int R1 = min(R0 + 8, n_rows - 1);
        const float* p0 = he + (size_t)R0 * FDIM;
        const float* p1 = he + (size_t)R1 * FDIM;
        #pragma unroll
        for (int kt = 0; kt < 4; kt++) {
            int c0 = 16 * kt + 2 * q, c1 = c0 + 8;
            float2 e;
            e = *(const float2*)(p0 + c0); split_pack(e.x, e.y, Ahi[mt][kt][0], Alo[mt][kt][0]);
            e = *(const float2*)(p1 + c0); split_pack(e.x, e.y, Ahi[mt][kt][1], Alo[mt][kt][1]);
            e = *(const float2*)(p0 + c1); split_pack(e.x, e.y, Ahi[mt][kt][2], Alo[mt][kt][2]);
            e = *(const float2*)(p1 + c1); split_pack(e.x, e.y, Ahi[mt][kt][3], Alo[mt][kt][3]);
        }
    }
    __syncthreads();   // W tiles ready

    // ---- per-epi-row attention params (rows r+8m of warp block) ----
    int Lm[4], basem[4];
    #pragma unroll
    for (int m = 0; m < 4; m++) {
        int grow = warpRow + r + 8 * m;
        int tm = grow % TLEN;
        int Lv = min(A, max(tm, 1));
        Lm[m] = Lv;
        basem[m] = tm - Lv;
    }

    // ---- prologue: D = H0 @ W1 (standalone GEMM into persistent D) ----
    float D[4][2][2][4];    // [ntp][mt][np][c]
    #pragma unroll
    for (int ntp = 0; ntp < 4; ntp++)
        gemm_chunk(D[ntp], Ahi, Alo, sW, ntp, r, q);

    // ================= Pass 1: recurrence + scores =================
    for (int a = 0; a < AMAX; a++) {
        // ---- epi1: A := sigmoid-split(D)   (D[ntp] chunk -> A[*][ntp][*]) ----
        #pragma unroll
        for (int ntp = 0; ntp < 4; ntp++) {
            #pragma unroll
            for (int mt = 0; mt < 2; mt++) {
                const float* e0 = D[ntp][mt][0];
                const float* e1 = D[ntp][mt][1];
                split_pack(sigmoidf(e0[0]), sigmoidf(e0[1]), Ahi[mt][ntp][0], Alo[mt][ntp][0]);
                split_pack(sigmoidf(e0[2]), sigmoidf(e0[3]), Ahi[mt][ntp][1], Alo[mt][ntp][1]);
                split_pack(sigmoidf(e1[0]), sigmoidf(e1[1]), Ahi[mt][ntp][2], Alo[mt][ntp][2]);
                split_pack(sigmoidf(e1[2]), sigmoidf(e1[3]), Ahi[mt][ntp][3], Alo[mt][ntp][3]);
            }
        }

        // ---- dual GEMM: D := H@W1 (next step), d2 -> score (consumed per chunk) ----
        const float* gp[4];
        #pragma unroll
        for (int m = 0; m < 4; m++) {
            int j = basem[m] + a;
            j = max(j, 0);
            gp[m] = bhe + (size_t)j * FDIM;
        }
        float p[4] = {0.f, 0.f, 0.f, 0.f};
        #pragma unroll
        for (int ntp = 0; ntp < 4; ntp++) {
            float d2[2][2][4];
            dual_chunk(D[ntp], d2, Ahi, Alo, sW, sW + 64 * WSTR, ntp, r, q);
            #pragma unroll
            for (int np = 0; np < 2; np++) {
                const int col = (2 * ntp + np) * 8 + 2 * q;
                #pragma unroll
                for (int m = 0; m < 4; m++) {
                    int mt = m >> 1, cp = (m & 1) * 2;
                    float y0 = sigmoidf(d2[mt][np][cp + 0]);
                    float y1 = sigmoidf(d2[mt][np][cp + 1]);
                    float2 g = *(const float2*)(gp[m] + col);
                    p[m] = fmaf(y0, g.x, fmaf(y1, g.y, p[m]));
                }
            }
        }
        #pragma unroll
        for (int m = 0; m < 4; m++) {
            p[m] += __shfl_xor_sync(0xFFFFFFFFu, p[m], 1);
            p[m] += __shfl_xor_sync(0xFFFFFFFFu, p[m], 2);
        }
        if (q == 0) {
            #pragma unroll
            for (int m = 0; m < 4; m++)
                sS[a * RPC + wid * 32 + r + 8 * m] = (a < Lm[m]) ? p[m] : -1e30f;
        }
    }
    __syncthreads();

    // ================= Pass 2: softmax + weighted gather (1 thread/row) =========
    {
        const int row = ctaRow0 + tid;
        if (row < n_rows) {
            const int t   = row % TLEN;
            const int L   = min(A, max(t, 1));
            const int bse = t - L;

            float mx = -1e30f;
            for (int a = 0; a < AMAX; a++) mx = fmaxf(mx, sS[a * RPC + tid]);

            float acc[FDIM];
            #pragma unroll
            for (int j = 0; j < FDIM; j++) acc[j] = 0.0f;
            float ssum = 0.0f;
            for (int a = 0; a < L; a++) {
                float w = __expf(sS[a * RPC + tid] - mx);
                ssum += w;
                int jrow = max(bse + a, 0);
                const float4* g = (const float4*)(bhe + (size_t)jrow * FDIM);
                #pragma unroll
                for (int c = 0; c < 16; c++) {
                    float4 gv = g[c];
                    acc[4*c+0] = fmaf(w, gv.x, acc[4*c+0]);
                    acc[4*c+1] = fmaf(w, gv.y, acc[4*c+1]);
                    acc[4*c+2] = fmaf(w, gv.z, acc[4*c+2]);
                    acc[4*c+3] = fmaf(w, gv.w, acc[4*c+3]);
                }
            }
            const float inv = __fdividef(1.0f, ssum);
            float4* o = (float4*)(out + (size_t)row * FDIM);
            #pragma unroll
            for (int c = 0; c < 16; c++) {
                float4 v;
                v.x = acc[4*c+0] * inv; v.y = acc[4*c+1] * inv;
                v.z = acc[4*c+2] * inv; v.w = acc[4*c+3] * inv;
                o[c] = v;
            }
        }
    }
}

extern "C" void kernel_launch(void* const* d_in, const int* in_sizes, int n_in,
                              void* d_out, int out_size)
{
    const float* he   = (const float*)d_in[0];
    const float* W1   = (const float*)d_in[1];
    const float* W2   = (const float*)d_in[2];
    const int*   alen = (n_in >= 4) ? (const int*)d_in[3] : nullptr;
    float*       out  = (float*)d_out;

    const int n_rows = in_sizes[0] / FDIM;   // B*T

    cudaFuncSetAttribute(ContextBlock_kernel,
                         cudaFuncAttributeMaxDynamicSharedMemorySize, SMEM_TOTAL);
    const int grid = (n_rows + RPC - 1) / RPC;
    ContextBlock_kernel<<<grid, TPB, SMEM_TOTAL>>>(he, W1, W2, alen, out, n_rows);
}